// round 6
// baseline (speedup 1.0000x reference)
#include <cuda_runtime.h>
#include <math.h>

#define NMAX 50000
#define EMAX 400000

// ---- scratch (__device__ globals; no allocation allowed) ----
__device__ float g_qnode[NMAX * 128];
__device__ float g_khm[NMAX * 128];
__device__ float g_kh[EMAX * 128];    // CSR-ordered per-edge key vectors
__device__ float g_a[EMAX * 8];       // CSR-ordered logits, then exp(a-m) in place
__device__ float g_agg[NMAX * 128];
__device__ float g_w1t[192 * 512];
__device__ int   g_deg[NMAX];
__device__ int   g_rowptr[NMAX + 1];
__device__ int   g_cursor[NMAX];
__device__ int   g_pos[EMAX];         // edge -> CSR slot

// ------------------------------------------------------------------
__global__ void tg_init_deg(int n) {
    int i = blockIdx.x * blockDim.x + threadIdx.x;
    if (i < n) g_deg[i] = 0;
}

__global__ void tg_hist(const int* __restrict__ dst, int e) {
    int i = blockIdx.x * blockDim.x + threadIdx.x;
    if (i < e) atomicAdd(&g_deg[dst[i]], 1);
}

// single-block (1024 thr) exclusive scan of g_deg -> g_rowptr/g_cursor
__global__ void tg_scan(int n) {
    __shared__ int wsum[32];
    int t = threadIdx.x;
    int ch = (n + 1023) >> 10;
    int lo = t * ch;
    int hi = lo + ch; if (hi > n) hi = n;
    int s = 0;
    for (int i = lo; i < hi; i++) s += g_deg[i];
    int v = s;
    #pragma unroll
    for (int off = 1; off < 32; off <<= 1) {
        int u = __shfl_up_sync(0xffffffffu, v, off);
        if ((t & 31) >= off) v += u;
    }
    if ((t & 31) == 31) wsum[t >> 5] = v;
    __syncthreads();
    if (t < 32) {
        int w = wsum[t];
        #pragma unroll
        for (int off = 1; off < 32; off <<= 1) {
            int u = __shfl_up_sync(0xffffffffu, w, off);
            if (t >= off) w += u;
        }
        wsum[t] = w;
    }
    __syncthreads();
    int excl = v - s + ((t >= 32) ? wsum[(t >> 5) - 1] : 0);
    int run = excl;
    for (int i = lo; i < hi; i++) {
        g_rowptr[i] = run; g_cursor[i] = run; run += g_deg[i];
    }
    if (t == 1023) g_rowptr[n] = run;
}

// assign each edge its CSR slot
__global__ void tg_scatter(const int* __restrict__ dst, int e) {
    int i = blockIdx.x * blockDim.x + threadIdx.x;
    if (i < e) g_pos[i] = atomicAdd(&g_cursor[dst[i]], 1);
}

__global__ void tg_w1t(const float* __restrict__ W1) {
    int i = blockIdx.x * blockDim.x + threadIdx.x;
    if (i < 512 * 192) {
        int h = i / 192, k = i - h * 192;
        g_w1t[k * 512 + h] = W1[i];
    }
}

// ------------------------------------------------------------------
// out[n][j] = sum_{m<64} memory[n][m]*W[j*ldw+m] + (bias_off>=0 ? W[j][bias..]·cos(time_b) : 0)
__global__ void __launch_bounds__(256) tg_node_linear(
        const float* __restrict__ mem,
        const float* __restrict__ W, int ldw, int bias_off,
        const float* __restrict__ time_b,
        int out_sel, int n) {
    __shared__ float WT[64 * 132];
    __shared__ float bs[128];
    __shared__ float ms[8][4][64];
    int tid = threadIdx.x;
    for (int idx = tid; idx < 128 * 64; idx += 256) {
        int m = idx & 63, j = idx >> 6;
        WT[m * 132 + j] = W[j * ldw + m];
    }
    if (tid < 128) {
        float b = 0.f;
        if (bias_off >= 0) {
            #pragma unroll
            for (int t = 0; t < 32; t++) b += W[tid * ldw + bias_off + t] * cosf(time_b[t]);
        }
        bs[tid] = b;
    }
    __syncthreads();
    int warp = tid >> 5, lane = tid & 31;
    int nbase = blockIdx.x * 32 + warp * 4;
    for (int idx = lane; idx < 256; idx += 32) {
        int i = idx >> 6, mm = idx & 63;
        int ni = nbase + i;
        ms[warp][i][mm] = (ni < n) ? mem[ni * 64 + mm] : 0.f;
    }
    __syncwarp();
    float4 z = make_float4(0.f, 0.f, 0.f, 0.f);
    float4 a0 = z, a1 = z, a2 = z, a3 = z;
    const float* wp = &WT[4 * lane];
    #pragma unroll 4
    for (int m = 0; m < 64; m++) {
        float4 w4 = *(const float4*)(wp + m * 132);
        float x0 = ms[warp][0][m], x1 = ms[warp][1][m];
        float x2 = ms[warp][2][m], x3 = ms[warp][3][m];
        a0.x += x0 * w4.x; a0.y += x0 * w4.y; a0.z += x0 * w4.z; a0.w += x0 * w4.w;
        a1.x += x1 * w4.x; a1.y += x1 * w4.y; a1.z += x1 * w4.z; a1.w += x1 * w4.w;
        a2.x += x2 * w4.x; a2.y += x2 * w4.y; a2.z += x2 * w4.z; a2.w += x2 * w4.w;
        a3.x += x3 * w4.x; a3.y += x3 * w4.y; a3.z += x3 * w4.z; a3.w += x3 * w4.w;
    }
    float4 b4 = *(const float4*)&bs[4 * lane];
    float* outp = out_sel ? g_khm : g_qnode;
    #define NL_STORE(AI, I) { int ni = nbase + (I); if (ni < n) { \
        float4 r; r.x = AI.x + b4.x; r.y = AI.y + b4.y; r.z = AI.z + b4.z; r.w = AI.w + b4.w; \
        *(float4*)&outp[ni * 128 + 4 * lane] = r; } }
    NL_STORE(a0, 0) NL_STORE(a1, 1) NL_STORE(a2, 2) NL_STORE(a3, 3)
    #undef NL_STORE
}

// ------------------------------------------------------------------
// kh = khm[src] + Wk[:,64:128]@[efeats ; cos(tdiff*w+b)];  a[h] = <qnode[dst], kh>_h
// results written to the edge's CSR slot g_pos[e] (coalesced reads downstream)
__global__ void __launch_bounds__(256) tg_edge(
        const int* __restrict__ src, const int* __restrict__ dst,
        const float* __restrict__ ts, const float* __restrict__ ef,
        const float* __restrict__ ets, const float* __restrict__ Wk,
        const float* __restrict__ time_w, const float* __restrict__ time_b,
        int e_total) {
    __shared__ float WT[64 * 132];     // WT[c][j] = Wk[j][64+c]
    __shared__ float ks[8][4][64];
    int tid = threadIdx.x;
    for (int idx = tid; idx < 128 * 64; idx += 256) {
        int c = idx & 63, j = idx >> 6;
        WT[c * 132 + j] = Wk[j * 128 + 64 + c];
    }
    __syncthreads();
    int warp = tid >> 5, lane = tid & 31;
    int ebase = (blockIdx.x * 8 + warp) * 4;
    for (int idx = lane; idx < 256; idx += 32) {
        int ei = idx >> 6, c = idx & 63;
        int e = ebase + ei;
        float v = 0.f;
        if (e < e_total) {
            if (c < 32) v = ef[e * 32 + c];
            else {
                float td = ets[e] - ts[src[e]];
                int t = c - 32;
                v = cosf(td * time_w[t] + time_b[t]);
            }
        }
        ks[warp][ei][c] = v;
    }
    __syncwarp();
    float4 z = make_float4(0.f, 0.f, 0.f, 0.f);
    float4 a0 = z, a1 = z, a2 = z, a3 = z;
    {
        int e = ebase;     if (e < e_total) a0 = *(const float4*)&g_khm[src[e] * 128 + 4 * lane];
        e = ebase + 1;     if (e < e_total) a1 = *(const float4*)&g_khm[src[e] * 128 + 4 * lane];
        e = ebase + 2;     if (e < e_total) a2 = *(const float4*)&g_khm[src[e] * 128 + 4 * lane];
        e = ebase + 3;     if (e < e_total) a3 = *(const float4*)&g_khm[src[e] * 128 + 4 * lane];
    }
    const float* wp = &WT[4 * lane];
    #pragma unroll 4
    for (int c = 0; c < 64; c++) {
        float4 w4 = *(const float4*)(wp + c * 132);
        float x0 = ks[warp][0][c], x1 = ks[warp][1][c];
        float x2 = ks[warp][2][c], x3 = ks[warp][3][c];
        a0.x += x0 * w4.x; a0.y += x0 * w4.y; a0.z += x0 * w4.z; a0.w += x0 * w4.w;
        a1.x += x1 * w4.x; a1.y += x1 * w4.y; a1.z += x1 * w4.z; a1.w += x1 * w4.w;
        a2.x += x2 * w4.x; a2.y += x2 * w4.y; a2.z += x2 * w4.z; a2.w += x2 * w4.w;
        a3.x += x3 * w4.x; a3.y += x3 * w4.y; a3.z += x3 * w4.z; a3.w += x3 * w4.w;
    }
    #define TG_EPI(AI, EI) { int e = ebase + (EI); \
        float4 q = (e < e_total) ? *(const float4*)&g_qnode[dst[e] * 128 + 4 * lane] : z; \
        float p = q.x * AI.x + q.y * AI.y + q.z * AI.z + q.w * AI.w; \
        p += __shfl_xor_sync(0xffffffffu, p, 1); \
        p += __shfl_xor_sync(0xffffffffu, p, 2); \
        if (e < e_total) { \
            int slot = g_pos[e]; \
            *(float4*)&g_kh[slot * 128 + 4 * lane] = AI; \
            if ((lane & 3) == 0) g_a[slot * 8 + (lane >> 2)] = p; } }
    TG_EPI(a0, 0) TG_EPI(a1, 1) TG_EPI(a2, 2) TG_EPI(a3, 3)
    #undef TG_EPI
}

// ------------------------------------------------------------------
// warp per node: per-head softmax + weighted aggregation over the node's
// contiguous CSR range [rowptr[n], rowptr[n+1]).
// Sum pass stores exp(a-m) back into g_a in place (computed exactly once
// per edge-head); weight pass just rescales the stored value.
__global__ void __launch_bounds__(256) tg_node_agg(int n) {
    int warp = threadIdx.x >> 5, lane = threadIdx.x & 31;
    int node = blockIdx.x * 8 + warp;
    if (node >= n) return;
    int s = g_rowptr[node], t = g_rowptr[node + 1];
    float m0 = -3.0e38f, m1 = m0, m2 = m0, m3 = m0, m4 = m0, m5 = m0, m6 = m0, m7 = m0;
    for (int i = s + lane; i < t; i += 32) {
        float4 x0 = *(const float4*)&g_a[i * 8];
        float4 x1 = *(const float4*)&g_a[i * 8 + 4];
        m0 = fmaxf(m0, x0.x); m1 = fmaxf(m1, x0.y); m2 = fmaxf(m2, x0.z); m3 = fmaxf(m3, x0.w);
        m4 = fmaxf(m4, x1.x); m5 = fmaxf(m5, x1.y); m6 = fmaxf(m6, x1.z); m7 = fmaxf(m7, x1.w);
    }
    #pragma unroll
    for (int off = 16; off > 0; off >>= 1) {
        m0 = fmaxf(m0, __shfl_xor_sync(0xffffffffu, m0, off));
        m1 = fmaxf(m1, __shfl_xor_sync(0xffffffffu, m1, off));
        m2 = fmaxf(m2, __shfl_xor_sync(0xffffffffu, m2, off));
        m3 = fmaxf(m3, __shfl_xor_sync(0xffffffffu, m3, off));
        m4 = fmaxf(m4, __shfl_xor_sync(0xffffffffu, m4, off));
        m5 = fmaxf(m5, __shfl_xor_sync(0xffffffffu, m5, off));
        m6 = fmaxf(m6, __shfl_xor_sync(0xffffffffu, m6, off));
        m7 = fmaxf(m7, __shfl_xor_sync(0xffffffffu, m7, off));
    }
    float s0 = 0.f, s1 = 0.f, s2 = 0.f, s3 = 0.f, s4 = 0.f, s5 = 0.f, s6 = 0.f, s7 = 0.f;
    for (int i = s + lane; i < t; i += 32) {
        float4 x0 = *(const float4*)&g_a[i * 8];
        float4 x1 = *(const float4*)&g_a[i * 8 + 4];
        x0.x = __expf(x0.x - m0); x0.y = __expf(x0.y - m1);
        x0.z = __expf(x0.z - m2); x0.w = __expf(x0.w - m3);
        x1.x = __expf(x1.x - m4); x1.y = __expf(x1.y - m5);
        x1.z = __expf(x1.z - m6); x1.w = __expf(x1.w - m7);
        s0 += x0.x; s1 += x0.y; s2 += x0.z; s3 += x0.w;
        s4 += x1.x; s5 += x1.y; s6 += x1.z; s7 += x1.w;
        *(float4*)&g_a[i * 8] = x0;          // in-place: logits -> exp(a-m)
        *(float4*)&g_a[i * 8 + 4] = x1;
    }
    #pragma unroll
    for (int off = 16; off > 0; off >>= 1) {
        s0 += __shfl_xor_sync(0xffffffffu, s0, off);
        s1 += __shfl_xor_sync(0xffffffffu, s1, off);
        s2 += __shfl_xor_sync(0xffffffffu, s2, off);
        s3 += __shfl_xor_sync(0xffffffffu, s3, off);
        s4 += __shfl_xor_sync(0xffffffffu, s4, off);
        s5 += __shfl_xor_sync(0xffffffffu, s5, off);
        s6 += __shfl_xor_sync(0xffffffffu, s6, off);
        s7 += __shfl_xor_sync(0xffffffffu, s7, off);
    }
    // each group of 4 lanes owns head myh; each lane owns 4 of its 16 dims
    int myh = lane >> 2;
    float ssum = s0;
    if (myh == 1) ssum = s1;
    else if (myh == 2) ssum = s2;
    else if (myh == 3) ssum = s3;
    else if (myh == 4) ssum = s4;
    else if (myh == 5) ssum = s5;
    else if (myh == 6) ssum = s6;
    else if (myh == 7) ssum = s7;
    float rscale = 0.25f / ssum;     // includes 1/sqrt(D)=0.25
    int doff = myh * 16 + (lane & 3) * 4;
    float4 acc = make_float4(0.f, 0.f, 0.f, 0.f);
    int i = s;
    for (; i + 2 <= t; i += 2) {        // sequential streaming reads
        float w0 = g_a[i * 8 + myh] * rscale;
        float w1 = g_a[(i + 1) * 8 + myh] * rscale;
        float4 k0 = *(const float4*)&g_kh[i * 128 + doff];
        float4 k1 = *(const float4*)&g_kh[(i + 1) * 128 + doff];
        acc.x += w0 * k0.x; acc.y += w0 * k0.y; acc.z += w0 * k0.z; acc.w += w0 * k0.w;
        acc.x += w1 * k1.x; acc.y += w1 * k1.y; acc.z += w1 * k1.z; acc.w += w1 * k1.w;
    }
    if (i < t) {
        float w0 = g_a[i * 8 + myh] * rscale;
        float4 k0 = *(const float4*)&g_kh[i * 128 + doff];
        acc.x += w0 * k0.x; acc.y += w0 * k0.y; acc.z += w0 * k0.z; acc.w += w0 * k0.w;
    }
    *(float4*)&g_agg[node * 128 + doff] = acc;
}

// ------------------------------------------------------------------
// fused 2-layer MLP: x=[agg(128);mem(64)] -> relu(x@W1.T+b1) -> @W2.T+b2
__global__ void __launch_bounds__(256) tg_mlp(
        const float* __restrict__ mem,
        const float* __restrict__ b1,
        const float* __restrict__ W2,
        const float* __restrict__ b2,
        float* __restrict__ out, int n) {
    __shared__ float xs[16][192];
    __shared__ float hs[16][512];
    int tid = threadIdx.x;
    int nb = blockIdx.x * 16;
    // load x tile: 16 nodes x (128 agg + 64 mem)
    for (int idx = tid; idx < 16 * 192; idx += 256) {
        int ni = idx / 192, c = idx - ni * 192;
        int gn = nb + ni;
        float v = 0.f;
        if (gn < n) v = (c < 128) ? g_agg[gn * 128 + c] : mem[gn * 64 + (c - 128)];
        xs[ni][c] = v;
    }
    __syncthreads();
    int hidt = tid & 127;        // owns hids 4*hidt..4*hidt+3
    int grp = tid >> 7;          // owns nodes grp*8..grp*8+7
    float4 acc[8];
    #pragma unroll
    for (int i = 0; i < 8; i++) acc[i] = make_float4(0.f, 0.f, 0.f, 0.f);
    const float* w1p = &g_w1t[4 * hidt];
    #pragma unroll 4
    for (int k = 0; k < 192; k++) {
        float4 w = *(const float4*)(w1p + k * 512);
        #pragma unroll
        for (int i = 0; i < 8; i++) {
            float xk = xs[grp * 8 + i][k];
            acc[i].x += xk * w.x; acc[i].y += xk * w.y;
            acc[i].z += xk * w.z; acc[i].w += xk * w.w;
        }
    }
    float4 bb = *(const float4*)&b1[4 * hidt];
    #pragma unroll
    for (int i = 0; i < 8; i++) {
        float4 h;
        h.x = fmaxf(acc[i].x + bb.x, 0.f);
        h.y = fmaxf(acc[i].y + bb.y, 0.f);
        h.z = fmaxf(acc[i].z + bb.z, 0.f);
        h.w = fmaxf(acc[i].w + bb.w, 0.f);
        *(float4*)&hs[grp * 8 + i][4 * hidt] = h;
    }
    __syncthreads();
    // layer 2: one output per thread (16 nodes x 16 dims)
    int ni = tid >> 4, d = tid & 15;
    int gn = nb + ni;
    if (gn < n) {
        float o = b2[d];
        const float* w2p = &W2[d * 512];
        const float* hp = &hs[ni][0];
        #pragma unroll 4
        for (int h = 0; h < 512; h += 4) {
            float4 w = *(const float4*)(w2p + h);
            float4 hv = *(const float4*)(hp + h);
            o += w.x * hv.x + w.y * hv.y + w.z * hv.z + w.w * hv.w;
        }
        out[gn * 16 + d] = o;
    }
}

// ------------------------------------------------------------------
extern "C" void kernel_launch(void* const* d_in, const int* in_sizes, int n_in,
                              void* d_out, int out_size) {
    const int*   src    = (const int*)d_in[0];
    const int*   dst    = (const int*)d_in[1];
    const float* memory = (const float*)d_in[2];
    const float* ts     = (const float*)d_in[3];
    const float* efeats = (const float*)d_in[4];
    const float* ets    = (const float*)d_in[5];
    const float* Wq     = (const float*)d_in[6];
    const float* Wk     = (const float*)d_in[7];
    const float* W1     = (const float*)d_in[8];
    const float* b1     = (const float*)d_in[9];
    const float* W2     = (const float*)d_in[10];
    const float* b2     = (const float*)d_in[11];
    const float* time_w = (const float*)d_in[12];
    const float* time_b = (const float*)d_in[13];
    float* out = (float*)d_out;

    int e = in_sizes[0];               // E
    int n = in_sizes[3];               // N (ts has N elements)

    tg_init_deg<<<(n + 255) / 256, 256>>>(n);
    tg_hist<<<(e + 255) / 256, 256>>>(dst, e);
    tg_scan<<<1, 1024>>>(n);
    tg_scatter<<<(e + 255) / 256, 256>>>(dst, e);
    tg_w1t<<<(512 * 192 + 255) / 256, 256>>>(W1);

    tg_node_linear<<<(n + 31) / 32, 256>>>(memory, Wq, 96, 64, time_b, 0, n);
    tg_node_linear<<<(n + 31) / 32, 256>>>(memory, Wk, 128, -1, time_b, 1, n);

    tg_edge<<<(e + 31) / 32, 256>>>(src, dst, ts, efeats, ets, Wk, time_w, time_b, e);
    tg_node_agg<<<(n + 7) / 8, 256>>>(n);
    tg_mlp<<<(n + 15) / 16, 256>>>(memory, b1, W2, b2, out, n);
}

// round 11
// speedup vs baseline: 1.0202x; 1.0202x over previous
#include <cuda_runtime.h>
#include <math.h>

#define NMAX 50000
#define EMAX 400000

// ---- scratch (__device__ globals; no allocation allowed) ----
__device__ float g_qnode[NMAX * 128];
__device__ float g_khm[NMAX * 128];
__device__ float g_kh[EMAX * 128];    // CSR-ordered per-edge key vectors
__device__ float g_a[EMAX * 8];       // CSR-ordered logits, then exp(a-m) in place
__device__ float g_agg[NMAX * 128];
__device__ float g_w1t[192 * 512];    // W1 transposed [k][hid]
__device__ float g_wkt[64 * 128];     // Wk[:,64:128] transposed: [c][j]
__device__ int   g_deg[NMAX];
__device__ int   g_rowptr[NMAX + 1];
__device__ int   g_cursor[NMAX];
__device__ int   g_pos[EMAX];         // edge -> CSR slot

// ------------------------------------------------------------------
__global__ void tg_init_deg(int n) {
    int i = blockIdx.x * blockDim.x + threadIdx.x;
    if (i < n) g_deg[i] = 0;
}

__global__ void tg_hist(const int* __restrict__ dst, int e) {
    int i = blockIdx.x * blockDim.x + threadIdx.x;
    if (i < e) atomicAdd(&g_deg[dst[i]], 1);
}

// single-block (1024 thr) exclusive scan of g_deg -> g_rowptr/g_cursor
__global__ void tg_scan(int n) {
    __shared__ int wsum[32];
    int t = threadIdx.x;
    int ch = (n + 1023) >> 10;
    int lo = t * ch;
    int hi = lo + ch; if (hi > n) hi = n;
    int s = 0;
    for (int i = lo; i < hi; i++) s += g_deg[i];
    int v = s;
    #pragma unroll
    for (int off = 1; off < 32; off <<= 1) {
        int u = __shfl_up_sync(0xffffffffu, v, off);
        if ((t & 31) >= off) v += u;
    }
    if ((t & 31) == 31) wsum[t >> 5] = v;
    __syncthreads();
    if (t < 32) {
        int w = wsum[t];
        #pragma unroll
        for (int off = 1; off < 32; off <<= 1) {
            int u = __shfl_up_sync(0xffffffffu, w, off);
            if (t >= off) w += u;
        }
        wsum[t] = w;
    }
    __syncthreads();
    int excl = v - s + ((t >= 32) ? wsum[(t >> 5) - 1] : 0);
    int run = excl;
    for (int i = lo; i < hi; i++) {
        g_rowptr[i] = run; g_cursor[i] = run; run += g_deg[i];
    }
    if (t == 1023) g_rowptr[n] = run;
}

// assign each edge its CSR slot
__global__ void tg_scatter(const int* __restrict__ dst, int e) {
    int i = blockIdx.x * blockDim.x + threadIdx.x;
    if (i < e) g_pos[i] = atomicAdd(&g_cursor[dst[i]], 1);
}

// transpose W1 -> g_w1t and Wk[:,64:128] -> g_wkt
__global__ void tg_prep_w(const float* __restrict__ W1, const float* __restrict__ Wk) {
    int i = blockIdx.x * blockDim.x + threadIdx.x;
    if (i < 512 * 192) {
        int h = i / 192, k = i - h * 192;
        g_w1t[k * 512 + h] = W1[i];
    } else if (i < 512 * 192 + 64 * 128) {
        int r = i - 512 * 192;
        int c = r >> 7, j = r & 127;       // c<64, j<128
        g_wkt[c * 128 + j] = Wk[j * 128 + 64 + c];
    }
}

// ------------------------------------------------------------------
// out[n][j] = sum_{m<64} memory[n][m]*W[j*ldw+m] + (bias_off>=0 ? W[j][bias..]·cos(time_b) : 0)
__global__ void __launch_bounds__(256) tg_node_linear(
        const float* __restrict__ mem,
        const float* __restrict__ W, int ldw, int bias_off,
        const float* __restrict__ time_b,
        int out_sel, int n) {
    __shared__ float WT[64 * 132];
    __shared__ float bs[128];
    __shared__ float ms[8][4][64];
    int tid = threadIdx.x;
    for (int idx = tid; idx < 128 * 64; idx += 256) {
        int m = idx & 63, j = idx >> 6;
        WT[m * 132 + j] = W[j * ldw + m];
    }
    if (tid < 128) {
        float b = 0.f;
        if (bias_off >= 0) {
            #pragma unroll
            for (int t = 0; t < 32; t++) b += W[tid * ldw + bias_off + t] * cosf(time_b[t]);
        }
        bs[tid] = b;
    }
    __syncthreads();
    int warp = tid >> 5, lane = tid & 31;
    int nbase = blockIdx.x * 32 + warp * 4;
    for (int idx = lane; idx < 256; idx += 32) {
        int i = idx >> 6, mm = idx & 63;
        int ni = nbase + i;
        ms[warp][i][mm] = (ni < n) ? mem[ni * 64 + mm] : 0.f;
    }
    __syncwarp();
    float4 z = make_float4(0.f, 0.f, 0.f, 0.f);
    float4 a0 = z, a1 = z, a2 = z, a3 = z;
    const float* wp = &WT[4 * lane];
    #pragma unroll 4
    for (int m = 0; m < 64; m++) {
        float4 w4 = *(const float4*)(wp + m * 132);
        float x0 = ms[warp][0][m], x1 = ms[warp][1][m];
        float x2 = ms[warp][2][m], x3 = ms[warp][3][m];
        a0.x += x0 * w4.x; a0.y += x0 * w4.y; a0.z += x0 * w4.z; a0.w += x0 * w4.w;
        a1.x += x1 * w4.x; a1.y += x1 * w4.y; a1.z += x1 * w4.z; a1.w += x1 * w4.w;
        a2.x += x2 * w4.x; a2.y += x2 * w4.y; a2.z += x2 * w4.z; a2.w += x2 * w4.w;
        a3.x += x3 * w4.x; a3.y += x3 * w4.y; a3.z += x3 * w4.z; a3.w += x3 * w4.w;
    }
    float4 b4 = *(const float4*)&bs[4 * lane];
    float* outp = out_sel ? g_khm : g_qnode;
    #define NL_STORE(AI, I) { int ni = nbase + (I); if (ni < n) { \
        float4 r; r.x = AI.x + b4.x; r.y = AI.y + b4.y; r.z = AI.z + b4.z; r.w = AI.w + b4.w; \
        *(float4*)&outp[ni * 128 + 4 * lane] = r; } }
    NL_STORE(a0, 0) NL_STORE(a1, 1) NL_STORE(a2, 2) NL_STORE(a3, 3)
    #undef NL_STORE
}

// ------------------------------------------------------------------
// kh = khm[src] + WkT@[efeats ; cos(tdiff*w+b)];  a[h] = <qnode[dst], kh>_h
// 8 edges per warp; weights streamed from L1/L2-resident g_wkt (no smem tile);
// edge features transposed in smem for float4-broadcast reads.
__global__ void __launch_bounds__(256) tg_edge(
        const int* __restrict__ src, const int* __restrict__ dst,
        const float* __restrict__ ts, const float* __restrict__ ef,
        const float* __restrict__ ets,
        const float* __restrict__ time_w, const float* __restrict__ time_b,
        int e_total) {
    __shared__ float ks[8][64][8];     // [warp][c][edge]
    int tid = threadIdx.x;
    int warp = tid >> 5, lane = tid & 31;
    int ebase = (blockIdx.x * 8 + warp) * 8;
    // fill 8 edges x 64 cols, transposed
    for (int idx = lane; idx < 512; idx += 32) {
        int ei = idx & 7, c = idx >> 3;
        int e = ebase + ei;
        float v = 0.f;
        if (e < e_total) {
            if (c < 32) v = ef[e * 32 + c];
            else {
                float td = ets[e] - ts[src[e]];
                int t = c - 32;
                v = __cosf(td * time_w[t] + time_b[t]);
            }
        }
        ks[warp][c][ei] = v;
    }
    __syncwarp();
    float4 z = make_float4(0.f, 0.f, 0.f, 0.f);
    float4 acc[8];
    #pragma unroll
    for (int ei = 0; ei < 8; ei++) {
        int e = ebase + ei;
        acc[ei] = (e < e_total) ? *(const float4*)&g_khm[src[e] * 128 + 4 * lane] : z;
    }
    const float* wkp = &g_wkt[4 * lane];
    #pragma unroll 2
    for (int c = 0; c < 64; c++) {
        float4 w4 = *(const float4*)(wkp + c * 128);
        float4 xlo = *(const float4*)&ks[warp][c][0];
        float4 xhi = *(const float4*)&ks[warp][c][4];
        acc[0].x += xlo.x * w4.x; acc[0].y += xlo.x * w4.y; acc[0].z += xlo.x * w4.z; acc[0].w += xlo.x * w4.w;
        acc[1].x += xlo.y * w4.x; acc[1].y += xlo.y * w4.y; acc[1].z += xlo.y * w4.z; acc[1].w += xlo.y * w4.w;
        acc[2].x += xlo.z * w4.x; acc[2].y += xlo.z * w4.y; acc[2].z += xlo.z * w4.z; acc[2].w += xlo.z * w4.w;
        acc[3].x += xlo.w * w4.x; acc[3].y += xlo.w * w4.y; acc[3].z += xlo.w * w4.z; acc[3].w += xlo.w * w4.w;
        acc[4].x += xhi.x * w4.x; acc[4].y += xhi.x * w4.y; acc[4].z += xhi.x * w4.z; acc[4].w += xhi.x * w4.w;
        acc[5].x += xhi.y * w4.x; acc[5].y += xhi.y * w4.y; acc[5].z += xhi.y * w4.z; acc[5].w += xhi.y * w4.w;
        acc[6].x += xhi.z * w4.x; acc[6].y += xhi.z * w4.y; acc[6].z += xhi.z * w4.z; acc[6].w += xhi.z * w4.w;
        acc[7].x += xhi.w * w4.x; acc[7].y += xhi.w * w4.y; acc[7].z += xhi.w * w4.z; acc[7].w += xhi.w * w4.w;
    }
    #pragma unroll
    for (int ei = 0; ei < 8; ei++) {
        int e = ebase + ei;
        if (e < e_total) {                    // warp-uniform branch
            float4 q = *(const float4*)&g_qnode[dst[e] * 128 + 4 * lane];
            float p = q.x * acc[ei].x + q.y * acc[ei].y + q.z * acc[ei].z + q.w * acc[ei].w;
            p += __shfl_xor_sync(0xffffffffu, p, 1);
            p += __shfl_xor_sync(0xffffffffu, p, 2);
            int slot = g_pos[e];
            *(float4*)&g_kh[slot * 128 + 4 * lane] = acc[ei];
            if ((lane & 3) == 0) g_a[slot * 8 + (lane >> 2)] = p;
        }
    }
}

// ------------------------------------------------------------------
// warp per node: per-head softmax + weighted aggregation over the node's
// contiguous CSR range. Sum pass stores exp(a-m) in place.
__global__ void __launch_bounds__(256) tg_node_agg(int n) {
    int warp = threadIdx.x >> 5, lane = threadIdx.x & 31;
    int node = blockIdx.x * 8 + warp;
    if (node >= n) return;
    int s = g_rowptr[node], t = g_rowptr[node + 1];
    float m0 = -3.0e38f, m1 = m0, m2 = m0, m3 = m0, m4 = m0, m5 = m0, m6 = m0, m7 = m0;
    for (int i = s + lane; i < t; i += 32) {
        float4 x0 = *(const float4*)&g_a[i * 8];
        float4 x1 = *(const float4*)&g_a[i * 8 + 4];
        m0 = fmaxf(m0, x0.x); m1 = fmaxf(m1, x0.y); m2 = fmaxf(m2, x0.z); m3 = fmaxf(m3, x0.w);
        m4 = fmaxf(m4, x1.x); m5 = fmaxf(m5, x1.y); m6 = fmaxf(m6, x1.z); m7 = fmaxf(m7, x1.w);
    }
    #pragma unroll
    for (int off = 16; off > 0; off >>= 1) {
        m0 = fmaxf(m0, __shfl_xor_sync(0xffffffffu, m0, off));
        m1 = fmaxf(m1, __shfl_xor_sync(0xffffffffu, m1, off));
        m2 = fmaxf(m2, __shfl_xor_sync(0xffffffffu, m2, off));
        m3 = fmaxf(m3, __shfl_xor_sync(0xffffffffu, m3, off));
        m4 = fmaxf(m4, __shfl_xor_sync(0xffffffffu, m4, off));
        m5 = fmaxf(m5, __shfl_xor_sync(0xffffffffu, m5, off));
        m6 = fmaxf(m6, __shfl_xor_sync(0xffffffffu, m6, off));
        m7 = fmaxf(m7, __shfl_xor_sync(0xffffffffu, m7, off));
    }
    float s0 = 0.f, s1 = 0.f, s2 = 0.f, s3 = 0.f, s4 = 0.f, s5 = 0.f, s6 = 0.f, s7 = 0.f;
    for (int i = s + lane; i < t; i += 32) {
        float4 x0 = *(const float4*)&g_a[i * 8];
        float4 x1 = *(const float4*)&g_a[i * 8 + 4];
        x0.x = __expf(x0.x - m0); x0.y = __expf(x0.y - m1);
        x0.z = __expf(x0.z - m2); x0.w = __expf(x0.w - m3);
        x1.x = __expf(x1.x - m4); x1.y = __expf(x1.y - m5);
        x1.z = __expf(x1.z - m6); x1.w = __expf(x1.w - m7);
        s0 += x0.x; s1 += x0.y; s2 += x0.z; s3 += x0.w;
        s4 += x1.x; s5 += x1.y; s6 += x1.z; s7 += x1.w;
        *(float4*)&g_a[i * 8] = x0;
        *(float4*)&g_a[i * 8 + 4] = x1;
    }
    #pragma unroll
    for (int off = 16; off > 0; off >>= 1) {
        s0 += __shfl_xor_sync(0xffffffffu, s0, off);
        s1 += __shfl_xor_sync(0xffffffffu, s1, off);
        s2 += __shfl_xor_sync(0xffffffffu, s2, off);
        s3 += __shfl_xor_sync(0xffffffffu, s3, off);
        s4 += __shfl_xor_sync(0xffffffffu, s4, off);
        s5 += __shfl_xor_sync(0xffffffffu, s5, off);
        s6 += __shfl_xor_sync(0xffffffffu, s6, off);
        s7 += __shfl_xor_sync(0xffffffffu, s7, off);
    }
    int myh = lane >> 2;
    float ssum = s0;
    if (myh == 1) ssum = s1;
    else if (myh == 2) ssum = s2;
    else if (myh == 3) ssum = s3;
    else if (myh == 4) ssum = s4;
    else if (myh == 5) ssum = s5;
    else if (myh == 6) ssum = s6;
    else if (myh == 7) ssum = s7;
    float rscale = 0.25f / ssum;     // includes 1/sqrt(D)=0.25
    int doff = myh * 16 + (lane & 3) * 4;
    float4 acc = make_float4(0.f, 0.f, 0.f, 0.f);
    int i = s;
    for (; i + 2 <= t; i += 2) {
        float w0 = g_a[i * 8 + myh] * rscale;
        float w1 = g_a[(i + 1) * 8 + myh] * rscale;
        float4 k0 = *(const float4*)&g_kh[i * 128 + doff];
        float4 k1 = *(const float4*)&g_kh[(i + 1) * 128 + doff];
        acc.x += w0 * k0.x; acc.y += w0 * k0.y; acc.z += w0 * k0.z; acc.w += w0 * k0.w;
        acc.x += w1 * k1.x; acc.y += w1 * k1.y; acc.z += w1 * k1.z; acc.w += w1 * k1.w;
    }
    if (i < t) {
        float w0 = g_a[i * 8 + myh] * rscale;
        float4 k0 = *(const float4*)&g_kh[i * 128 + doff];
        acc.x += w0 * k0.x; acc.y += w0 * k0.y; acc.z += w0 * k0.z; acc.w += w0 * k0.w;
    }
    *(float4*)&g_agg[node * 128 + doff] = acc;
}

// ------------------------------------------------------------------
// fused 2-layer MLP: x=[agg(128);mem(64)] -> relu(x@W1.T+b1) -> @W2.T+b2
__global__ void __launch_bounds__(256) tg_mlp(
        const float* __restrict__ mem,
        const float* __restrict__ b1,
        const float* __restrict__ W2,
        const float* __restrict__ b2,
        float* __restrict__ out, int n) {
    __shared__ float xs[16][192];
    __shared__ float hs[16][512];
    int tid = threadIdx.x;
    int nb = blockIdx.x * 16;
    for (int idx = tid; idx < 16 * 192; idx += 256) {
        int ni = idx / 192, c = idx - ni * 192;
        int gn = nb + ni;
        float v = 0.f;
        if (gn < n) v = (c < 128) ? g_agg[gn * 128 + c] : mem[gn * 64 + (c - 128)];
        xs[ni][c] = v;
    }
    __syncthreads();
    int hidt = tid & 127;
    int grp = tid >> 7;
    float4 acc[8];
    #pragma unroll
    for (int i = 0; i < 8; i++) acc[i] = make_float4(0.f, 0.f, 0.f, 0.f);
    const float* w1p = &g_w1t[4 * hidt];
    #pragma unroll 4
    for (int k = 0; k < 192; k++) {
        float4 w = *(const float4*)(w1p + k * 512);
        #pragma unroll
        for (int i = 0; i < 8; i++) {
            float xk = xs[grp * 8 + i][k];
            acc[i].x += xk * w.x; acc[i].y += xk * w.y;
            acc[i].z += xk * w.z; acc[i].w += xk * w.w;
        }
    }
    float4 bb = *(const float4*)&b1[4 * hidt];
    #pragma unroll
    for (int i = 0; i < 8; i++) {
        float4 h;
        h.x = fmaxf(acc[i].x + bb.x, 0.f);
        h.y = fmaxf(acc[i].y + bb.y, 0.f);
        h.z = fmaxf(acc[i].z + bb.z, 0.f);
        h.w = fmaxf(acc[i].w + bb.w, 0.f);
        *(float4*)&hs[grp * 8 + i][4 * hidt] = h;
    }
    __syncthreads();
    int ni = tid >> 4, d = tid & 15;
    int gn = nb + ni;
    if (gn < n) {
        float o = b2[d];
        const float* w2p = &W2[d * 512];
        const float* hp = &hs[ni][0];
        #pragma unroll 4
        for (int h = 0; h < 512; h += 4) {
            float4 w = *(const float4*)(w2p + h);
            float4 hv = *(const float4*)(hp + h);
            o += w.x * hv.x + w.y * hv.y + w.z * hv.z + w.w * hv.w;
        }
        out[gn * 16 + d] = o;
    }
}

// ------------------------------------------------------------------
extern "C" void kernel_launch(void* const* d_in, const int* in_sizes, int n_in,
                              void* d_out, int out_size) {
    const int*   src    = (const int*)d_in[0];
    const int*   dst    = (const int*)d_in[1];
    const float* memory = (const float*)d_in[2];
    const float* ts     = (const float*)d_in[3];
    const float* efeats = (const float*)d_in[4];
    const float* ets    = (const float*)d_in[5];
    const float* Wq     = (const float*)d_in[6];
    const float* Wk     = (const float*)d_in[7];
    const float* W1     = (const float*)d_in[8];
    const float* b1     = (const float*)d_in[9];
    const float* W2     = (const float*)d_in[10];
    const float* b2     = (const float*)d_in[11];
    const float* time_w = (const float*)d_in[12];
    const float* time_b = (const float*)d_in[13];
    float* out = (float*)d_out;

    int e = in_sizes[0];               // E
    int n = in_sizes[3];               // N (ts has N elements)

    tg_init_deg<<<(n + 255) / 256, 256>>>(n);
    tg_hist<<<(e + 255) / 256, 256>>>(dst, e);
    tg_scan<<<1, 1024>>>(n);
    tg_scatter<<<(e + 255) / 256, 256>>>(dst, e);
    tg_prep_w<<<(512 * 192 + 64 * 128 + 255) / 256, 256>>>(W1, Wk);

    tg_node_linear<<<(n + 31) / 32, 256>>>(memory, Wq, 96, 64, time_b, 0, n);
    tg_node_linear<<<(n + 31) / 32, 256>>>(memory, Wk, 128, -1, time_b, 1, n);

    tg_edge<<<(e + 63) / 64, 256>>>(src, dst, ts, efeats, ets, time_w, time_b, e);
    tg_node_agg<<<(n + 7) / 8, 256>>>(n);
    tg_mlp<<<(n + 15) / 16, 256>>>(memory, b1, W2, b2, out, n);
}